// round 2
// baseline (speedup 1.0000x reference)
#include <cuda_runtime.h>
#include <cstdint>

// Problem constants (fixed by the reference: [8, 2048, 256] fp32)
#define BATCH 8
#define SEQ   2048
#define KDIM  256

#define BM   128          // output tile (rows == cols)
#define BK   16           // k chunk
#define NT   (SEQ / BM)   // 16 tiles per dim
#define NPAIR (NT * (NT + 1) / 2)  // 136 triangular block pairs
#define LDA  132          // smem row pitch (pad 4 floats: 16B-aligned rows)

// Scratch for per-row squared norms (device global: no allocation allowed)
__device__ float g_norms[BATCH * SEQ];

// ---------------------------------------------------------------------------
// packed f32x2 helpers (ptxas never auto-fuses; PTX only)
// ---------------------------------------------------------------------------
__device__ __forceinline__ unsigned long long pack2(float lo, float hi) {
    unsigned long long r;
    asm("mov.b64 %0, {%1, %2};" : "=l"(r) : "f"(lo), "f"(hi));
    return r;
}
__device__ __forceinline__ void unpack2(unsigned long long v, float& lo, float& hi) {
    asm("mov.b64 {%0, %1}, %2;" : "=f"(lo), "=f"(hi) : "l"(v));
}
__device__ __forceinline__ unsigned long long ffma2(unsigned long long a,
                                                    unsigned long long b,
                                                    unsigned long long c) {
    unsigned long long d;
    asm("fma.rn.f32x2 %0, %1, %2, %3;" : "=l"(d) : "l"(a), "l"(b), "l"(c));
    return d;
}

// ---------------------------------------------------------------------------
// Kernel 1: per-row squared norms. 8 warps/block, one warp per row.
// KDIM=256 -> 64 float4 per row -> 2 float4 per lane.
// ---------------------------------------------------------------------------
__global__ void norms_kernel(const float* __restrict__ x) {
    int row  = blockIdx.x * 8 + (threadIdx.x >> 5);
    int lane = threadIdx.x & 31;
    if (row >= BATCH * SEQ) return;
    const float4* p = (const float4*)(x + (size_t)row * KDIM);
    float s = 0.f;
#pragma unroll
    for (int i = 0; i < 2; i++) {
        float4 v = p[lane + 32 * i];
        s += v.x * v.x + v.y * v.y + v.z * v.z + v.w * v.w;
    }
#pragma unroll
    for (int o = 16; o; o >>= 1) s += __shfl_xor_sync(0xffffffffu, s, o);
    if (lane == 0) g_norms[row] = s;
}

// ---------------------------------------------------------------------------
// Kernel 2: symmetric tiled distance kernel.
// Grid: (NPAIR, BATCH). Each CTA owns the (ti, tj>=ti) 128x128 tile of
// D[b] = n_i + n_j - 2 * X X^T, and mirror-writes the (tj, ti) tile too.
// ---------------------------------------------------------------------------
__global__ __launch_bounds__(256, 2)
void dist_kernel(const float* __restrict__ x, float* __restrict__ out) {
    __shared__ float As[BK][LDA];   // As[k][i]  (i = row within tile)
    __shared__ float Bs[BK][LDA];   // Bs[k][j]

    const int b = blockIdx.y;
    int p = blockIdx.x;
    int ti = 0;
    while (p >= NT - ti) { p -= NT - ti; ti++; }
    const int tj = ti + p;

    const float* xb = x + (size_t)b * SEQ * KDIM;
    const int i0 = ti * BM;
    const int j0 = tj * BM;

    const int tid = threadIdx.x;
    const int tx = tid & 15;       // 16 cols of threads -> j
    const int ty = tid >> 4;       // 16 rows of threads -> i

    // global->smem loader mapping: 256 threads, each loads float4 of 4 k's
    const int lrow = tid >> 2;          // 0..63 (two passes cover 128 rows)
    const int lc4  = (tid & 3) * 4;     // k offset within chunk: 0,4,8,12

    // Accumulators: f32x2 pairs over the ROW dimension.
    // acc[r2][c]: lo = G[2*r2][c], hi = G[2*r2+1][c]
    unsigned long long acc[4][8];
#pragma unroll
    for (int r = 0; r < 4; r++)
#pragma unroll
        for (int c = 0; c < 8; c++) acc[r][c] = 0ull;

    for (int k0 = 0; k0 < KDIM; k0 += BK) {
#pragma unroll
        for (int half = 0; half < 2; half++) {
            const int row = lrow + 64 * half;
            float4 va = *(const float4*)(xb + (size_t)(i0 + row) * KDIM + k0 + lc4);
            As[lc4 + 0][row] = va.x;
            As[lc4 + 1][row] = va.y;
            As[lc4 + 2][row] = va.z;
            As[lc4 + 3][row] = va.w;
            float4 vb = *(const float4*)(xb + (size_t)(j0 + row) * KDIM + k0 + lc4);
            Bs[lc4 + 0][row] = vb.x;
            Bs[lc4 + 1][row] = vb.y;
            Bs[lc4 + 2][row] = vb.z;
            Bs[lc4 + 3][row] = vb.w;
        }
        __syncthreads();

#pragma unroll
        for (int k = 0; k < BK; k++) {
            // A: 8 row values as 4 packed pairs, straight from smem (no packing)
            unsigned long long a2[4];
            {
                const ulonglong2* ap = (const ulonglong2*)&As[k][ty * 8];
                ulonglong2 v0 = ap[0];
                ulonglong2 v1 = ap[1];
                a2[0] = v0.x; a2[1] = v0.y; a2[2] = v1.x; a2[3] = v1.y;
            }
            // B: 8 col values, broadcast-packed {b,b}
            unsigned long long b2[8];
            {
                const float4* bp = (const float4*)&Bs[k][tx * 8];
                float4 v0 = bp[0];
                float4 v1 = bp[1];
                b2[0] = pack2(v0.x, v0.x); b2[1] = pack2(v0.y, v0.y);
                b2[2] = pack2(v0.z, v0.z); b2[3] = pack2(v0.w, v0.w);
                b2[4] = pack2(v1.x, v1.x); b2[5] = pack2(v1.y, v1.y);
                b2[6] = pack2(v1.z, v1.z); b2[7] = pack2(v1.w, v1.w);
            }
#pragma unroll
            for (int r = 0; r < 4; r++)
#pragma unroll
                for (int c = 0; c < 8; c++)
                    acc[r][c] = ffma2(a2[r], b2[c], acc[r][c]);
        }
        __syncthreads();
    }

    // Epilogue: d = max(ni + nj - 2*g, 0)
    const float* nb = g_norms + b * SEQ;
    float ni[8], nj[8];
#pragma unroll
    for (int r = 0; r < 8; r++) ni[r] = nb[i0 + ty * 8 + r];
#pragma unroll
    for (int c = 0; c < 8; c++) nj[c] = nb[j0 + tx * 8 + c];

    float* ob = out + (size_t)b * SEQ * SEQ;
    const bool mirror = (ti != tj);

#pragma unroll
    for (int r2 = 0; r2 < 4; r2++) {
        float dlo[8], dhi[8];
#pragma unroll
        for (int c = 0; c < 8; c++) {
            float glo, ghi;
            unpack2(acc[r2][c], glo, ghi);
            dlo[c] = fmaxf(ni[2 * r2 + 0] + nj[c] - 2.f * glo, 0.f);
            dhi[c] = fmaxf(ni[2 * r2 + 1] + nj[c] - 2.f * ghi, 0.f);
        }
        // normal-orientation rows: coalesced float4 stores
        {
            float4* d0 = (float4*)(ob + (size_t)(i0 + ty * 8 + 2 * r2 + 0) * SEQ + j0 + tx * 8);
            d0[0] = make_float4(dlo[0], dlo[1], dlo[2], dlo[3]);
            d0[1] = make_float4(dlo[4], dlo[5], dlo[6], dlo[7]);
            float4* d1 = (float4*)(ob + (size_t)(i0 + ty * 8 + 2 * r2 + 1) * SEQ + j0 + tx * 8);
            d1[0] = make_float4(dhi[0], dhi[1], dhi[2], dhi[3]);
            d1[1] = make_float4(dhi[4], dhi[5], dhi[6], dhi[7]);
        }
        // mirror tile (D symmetric): per (c) write {lo,hi} as one float2 -> full
        // 32B sector utilization even though sectors are scattered.
        if (mirror) {
#pragma unroll
            for (int c = 0; c < 8; c++) {
                float2* dm = (float2*)(ob + (size_t)(j0 + tx * 8 + c) * SEQ +
                                       i0 + ty * 8 + 2 * r2);
                *dm = make_float2(dlo[c], dhi[c]);
            }
        }
    }
}

// ---------------------------------------------------------------------------
extern "C" void kernel_launch(void* const* d_in, const int* in_sizes, int n_in,
                              void* d_out, int out_size) {
    const float* x = (const float*)d_in[0];
    float* out = (float*)d_out;
    (void)in_sizes; (void)n_in; (void)out_size;

    norms_kernel<<<(BATCH * SEQ + 7) / 8, 256>>>(x);
    dist_kernel<<<dim3(NPAIR, BATCH), 256>>>(x, out);
}

// round 6
// speedup vs baseline: 2.4766x; 2.4766x over previous
#include <cuda_runtime.h>
#include <cstdint>

// Problem: [8, 2048, 256] fp32 -> pairwise sq. distances [8, 2048, 2048]
#define BATCH 8
#define SEQ   2048
#define KDIM  256
#define BM    128
#define NT    (SEQ / BM)             // 16
#define NPAIR (NT * (NT + 1) / 2)    // 136 triangular tile pairs
#define BK    32                     // K floats per chunk
#define NCHUNK (KDIM / BK)           // 8

#define PITCH      36                       // floats per smem row (144B)
#define TILE_F     (BM * PITCH)             // 4608 floats per tile
#define STAGE_F    (2 * TILE_F)             // A + B = 9216 floats per stage
#define SMEM_BYTES (2 * STAGE_F * 4)        // 73728 B (2 stages)
// epilogue transpose staging (128 x 132 = 16896 floats) aliases the stages

__device__ float g_norms[BATCH * SEQ];

// ---------------------------------------------------------------------------
// PTX helpers (all sm_80-era: compile clean for plain compute_100)
// ---------------------------------------------------------------------------
__device__ __forceinline__ uint32_t smem_u32(const void* p) {
    uint32_t a;
    asm("{ .reg .u64 t; cvta.to.shared.u64 t, %1; cvt.u32.u64 %0, t; }"
        : "=r"(a) : "l"(p));
    return a;
}
__device__ __forceinline__ void cp16(uint32_t dst, const void* src) {
    asm volatile("cp.async.cg.shared.global [%0], [%1], 16;"
                 :: "r"(dst), "l"(src) : "memory");
}
#define CP_COMMIT() asm volatile("cp.async.commit_group;" ::: "memory")
#define CP_WAIT(n)  asm volatile("cp.async.wait_group %0;" :: "n"(n) : "memory")

__device__ __forceinline__ uint32_t f2tf(float x) {
    uint32_t u;
    asm("cvt.rna.tf32.f32 %0, %1;" : "=r"(u) : "f"(x));
    return u;
}
__device__ __forceinline__ void mma_tf32(float* c, const uint32_t* a,
                                         const uint32_t* b) {
    asm volatile(
        "mma.sync.aligned.m16n8k8.row.col.f32.tf32.tf32.f32 "
        "{%0,%1,%2,%3}, {%4,%5,%6,%7}, {%8,%9}, {%0,%1,%2,%3};"
        : "+f"(c[0]), "+f"(c[1]), "+f"(c[2]), "+f"(c[3])
        : "r"(a[0]), "r"(a[1]), "r"(a[2]), "r"(a[3]), "r"(b[0]), "r"(b[1]));
}

// ---------------------------------------------------------------------------
// Kernel 1: per-row squared norms (fp32 exact)
// ---------------------------------------------------------------------------
__global__ void norms_kernel(const float* __restrict__ x) {
    int row  = blockIdx.x * 8 + (threadIdx.x >> 5);
    int lane = threadIdx.x & 31;
    if (row >= BATCH * SEQ) return;
    const float4* p = (const float4*)(x + (size_t)row * KDIM);
    float s = 0.f;
#pragma unroll
    for (int i = 0; i < 2; i++) {
        float4 v = p[lane + 32 * i];
        s += v.x * v.x + v.y * v.y + v.z * v.z + v.w * v.w;
    }
#pragma unroll
    for (int o = 16; o; o >>= 1) s += __shfl_xor_sync(0xffffffffu, s, o);
    if (lane == 0) g_norms[row] = s;
}

// ---------------------------------------------------------------------------
// Kernel 2: tf32 mma.sync Gram + distance epilogue, symmetric tile pairs.
// 256 threads, warp grid 2(M) x 4(N), warp tile 64x32, mma m16n8k8.
// ---------------------------------------------------------------------------
__global__ __launch_bounds__(256, 2)
void dist_mma(const float* __restrict__ x, float* __restrict__ out) {
    extern __shared__ float smf[];
    __shared__ float s_ni[BM], s_nj[BM];
    const uint32_t smb = smem_u32(smf);

    const int tid  = threadIdx.x;
    const int lane = tid & 31;
    const int w    = tid >> 5;
    const int wm   = w & 1;          // warp row (2 x 64)
    const int wn   = w >> 1;         // warp col (4 x 32)
    const int gid  = lane >> 2;      // 0..7
    const int tig  = lane & 3;       // 0..3

    const int b = blockIdx.y;
    int p = blockIdx.x;
    int ti = 0;
    while (p >= NT - ti) { p -= NT - ti; ti++; }
    const int tj = ti + p;
    const int i0 = ti * BM, j0 = tj * BM;
    const bool diag = (ti == tj);

    const float* xb = x + (size_t)b * SEQ * KDIM;
    float* ob = out + (size_t)b * SEQ * SEQ;

    // preload norms into static smem (published by later syncthreads)
    if (tid < BM) s_ni[tid] = g_norms[b * SEQ + i0 + tid];
    else          s_nj[tid - BM] = g_norms[b * SEQ + j0 + tid - BM];

    // chunk loader: A tile rows i0.., B tile rows j0.., both [row][k] pitch 36
    auto load_chunk = [&](int c, int s) {
        const uint32_t base = smb + (uint32_t)s * (STAGE_F * 4);
#pragma unroll
        for (int t = 0; t < 4; t++) {
            const int idx = tid + t * 256;          // 1024 granules per tile
            const int row = idx >> 3;
            const int g   = idx & 7;
            const uint32_t off = (uint32_t)(row * (PITCH * 4) + g * 16);
            cp16(base + off,
                 xb + (size_t)(i0 + row) * KDIM + c * BK + g * 4);
            cp16(base + TILE_F * 4 + off,
                 xb + (size_t)(j0 + row) * KDIM + c * BK + g * 4);
        }
        CP_COMMIT();
    };

    float acc[4][4][4];
#pragma unroll
    for (int mt = 0; mt < 4; mt++)
#pragma unroll
        for (int nt = 0; nt < 4; nt++)
#pragma unroll
            for (int q = 0; q < 4; q++) acc[mt][nt][q] = 0.f;

    load_chunk(0, 0);
    load_chunk(1, 1);

    for (int c = 0; c < NCHUNK; c++) {
        if (c < NCHUNK - 1) { CP_WAIT(1); } else { CP_WAIT(0); }
        __syncthreads();

        const float* As = smf + (c & 1) * STAGE_F + wm * 64 * PITCH;
        const float* Bs = smf + (c & 1) * STAGE_F + TILE_F + wn * 32 * PITCH;

#pragma unroll
        for (int kk = 0; kk < 4; kk++) {
            uint32_t af[4][4], bf[4][2];
#pragma unroll
            for (int mt = 0; mt < 4; mt++) {
                const float* ap = As + (mt * 16 + gid) * PITCH + kk * 8 + tig;
                af[mt][0] = f2tf(ap[0]);
                af[mt][1] = f2tf(ap[8 * PITCH]);
                af[mt][2] = f2tf(ap[4]);
                af[mt][3] = f2tf(ap[8 * PITCH + 4]);
            }
#pragma unroll
            for (int nt = 0; nt < 4; nt++) {
                const float* bp = Bs + (nt * 8 + gid) * PITCH + kk * 8 + tig;
                bf[nt][0] = f2tf(bp[0]);
                bf[nt][1] = f2tf(bp[4]);
            }
#pragma unroll
            for (int mt = 0; mt < 4; mt++)
#pragma unroll
                for (int nt = 0; nt < 4; nt++)
                    mma_tf32(acc[mt][nt], af[mt], bf[nt]);
        }
        __syncthreads();
        if (c + 2 < NCHUNK) load_chunk(c + 2, c & 1);
    }

    // -----------------------------------------------------------------------
    // Epilogue. Fragment (mt,nt): rows r0/r0+8, cols jc/jc+1.
    // Normal tile: direct float2 stores. Mirror: transpose-stage into the
    // (dead) pipeline smem [col][row] pitch 132, then coalesced float4 out.
    // -----------------------------------------------------------------------
    float* sd = smf;   // 128 x 132 floats = 16896 <= 18432 available
#pragma unroll
    for (int mt = 0; mt < 4; mt++) {
        const int r0 = wm * 64 + mt * 16 + gid;
        const int r1 = r0 + 8;
        const float n0 = s_ni[r0], n1 = s_ni[r1];
#pragma unroll
        for (int nt = 0; nt < 4; nt++) {
            const int jc = wn * 32 + nt * 8 + tig * 2;
            const float m0 = s_nj[jc], m1 = s_nj[jc + 1];
            float d00 = fmaxf(n0 + m0 - 2.f * acc[mt][nt][0], 0.f);
            float d01 = fmaxf(n0 + m1 - 2.f * acc[mt][nt][1], 0.f);
            float d10 = fmaxf(n1 + m0 - 2.f * acc[mt][nt][2], 0.f);
            float d11 = fmaxf(n1 + m1 - 2.f * acc[mt][nt][3], 0.f);
            if (diag) {
                if (r0 == jc)     d00 = 0.f;
                if (r0 == jc + 1) d01 = 0.f;
                if (r1 == jc)     d10 = 0.f;
                if (r1 == jc + 1) d11 = 0.f;
            }
            *(float2*)(ob + (size_t)(i0 + r0) * SEQ + j0 + jc) =
                make_float2(d00, d01);
            *(float2*)(ob + (size_t)(i0 + r1) * SEQ + j0 + jc) =
                make_float2(d10, d11);
            if (!diag) {
                sd[jc * 132 + r0]       = d00;
                sd[(jc + 1) * 132 + r0] = d01;
                sd[jc * 132 + r1]       = d10;
                sd[(jc + 1) * 132 + r1] = d11;
            }
        }
    }

    if (!diag) {
        __syncthreads();
        const int jr = tid >> 1;            // mirror row 0..127
        const int h  = tid & 1;             // half: 64 floats
        const float4* srow = (const float4*)(sd + jr * 132 + h * 64);
        float4* drow = (float4*)(ob + (size_t)(j0 + jr) * SEQ + i0 + h * 64);
#pragma unroll
        for (int q = 0; q < 16; q++) drow[q] = srow[q];
    }
}

// ---------------------------------------------------------------------------
extern "C" void kernel_launch(void* const* d_in, const int* in_sizes, int n_in,
                              void* d_out, int out_size) {
    const float* x = (const float*)d_in[0];
    float* out = (float*)d_out;
    (void)in_sizes; (void)n_in; (void)out_size;

    cudaFuncSetAttribute(dist_mma, cudaFuncAttributeMaxDynamicSharedMemorySize,
                         SMEM_BYTES);
    norms_kernel<<<(BATCH * SEQ + 7) / 8, 256>>>(x);
    dist_mma<<<dim3(NPAIR, BATCH), 256, SMEM_BYTES>>>(x, out);
}

// round 7
// speedup vs baseline: 2.7372x; 1.1052x over previous
#include <cuda_runtime.h>
#include <cstdint>

// Problem: [8, 2048, 256] fp32 -> pairwise sq. distances [8, 2048, 2048]
#define BATCH 8
#define SEQ   2048
#define KDIM  256
#define BM    128
#define NT    (SEQ / BM)             // 16
#define NPAIR (NT * (NT + 1) / 2)    // 136 triangular tile pairs
#define BK    32                     // K floats per chunk
#define NCHUNK (KDIM / BK)           // 8

#define PITCH      36                       // floats per smem row (144B)
#define TILE_F     (BM * PITCH)             // 4608 floats per tile
#define STAGE_F    (2 * TILE_F)             // A + B = 9216 floats per stage
#define SMEM_BYTES (2 * STAGE_F * 4)        // 73728 B (2 stages)
// epilogue transpose staging (128 x 132 = 16896 floats) aliases the stages

__device__ float g_norms[BATCH * SEQ];

// ---------------------------------------------------------------------------
// PTX helpers (sm_80-era only: must compile for plain compute_100)
// ---------------------------------------------------------------------------
__device__ __forceinline__ uint32_t smem_u32(const void* p) {
    uint32_t a;
    asm("{ .reg .u64 t; cvta.to.shared.u64 t, %1; cvt.u32.u64 %0, t; }"
        : "=r"(a) : "l"(p));
    return a;
}
__device__ __forceinline__ void cp16(uint32_t dst, const void* src) {
    asm volatile("cp.async.cg.shared.global [%0], [%1], 16;"
                 :: "r"(dst), "l"(src) : "memory");
}
#define CP_COMMIT() asm volatile("cp.async.commit_group;" ::: "memory")
#define CP_WAIT(n)  asm volatile("cp.async.wait_group %0;" :: "n"(n) : "memory")

__device__ __forceinline__ void ldsm_x4(uint32_t addr, uint32_t* r) {
    asm volatile("ldmatrix.sync.aligned.m8n8.x4.shared.b16 {%0,%1,%2,%3}, [%4];"
                 : "=r"(r[0]), "=r"(r[1]), "=r"(r[2]), "=r"(r[3]) : "r"(addr));
}
__device__ __forceinline__ void ldsm_x2(uint32_t addr, uint32_t* r) {
    asm volatile("ldmatrix.sync.aligned.m8n8.x2.shared.b16 {%0,%1}, [%2];"
                 : "=r"(r[0]), "=r"(r[1]) : "r"(addr));
}

// mma tf32: operands carry raw fp32 bits (HW truncates to tf32 mantissa)
__device__ __forceinline__ void mma_tf32(float* c, const uint32_t* a,
                                         const uint32_t* b) {
    asm volatile(
        "mma.sync.aligned.m16n8k8.row.col.f32.tf32.tf32.f32 "
        "{%0,%1,%2,%3}, {%4,%5,%6,%7}, {%8,%9}, {%0,%1,%2,%3};"
        : "+f"(c[0]), "+f"(c[1]), "+f"(c[2]), "+f"(c[3])
        : "r"(a[0]), "r"(a[1]), "r"(a[2]), "r"(a[3]), "r"(b[0]), "r"(b[1]));
}

// ---------------------------------------------------------------------------
// Kernel 1: per-row squared norms (fp32 exact)
// ---------------------------------------------------------------------------
__global__ void norms_kernel(const float* __restrict__ x) {
    int row  = blockIdx.x * 8 + (threadIdx.x >> 5);
    int lane = threadIdx.x & 31;
    if (row >= BATCH * SEQ) return;
    const float4* p = (const float4*)(x + (size_t)row * KDIM);
    float s = 0.f;
#pragma unroll
    for (int i = 0; i < 2; i++) {
        float4 v = p[lane + 32 * i];
        s += v.x * v.x + v.y * v.y + v.z * v.z + v.w * v.w;
    }
#pragma unroll
    for (int o = 16; o; o >>= 1) s += __shfl_xor_sync(0xffffffffu, s, o);
    if (lane == 0) g_norms[row] = s;
}

// ---------------------------------------------------------------------------
// Kernel 2: tf32 mma.sync Gram + distance epilogue, symmetric tile pairs.
// 256 threads, warp grid 2(M) x 4(N), warp tile 64x32, mma m16n8k8.
// Fragments loaded with ldmatrix (tf32-as-2xb16 trick), raw fp32 fed to MMA.
// ---------------------------------------------------------------------------
__global__ __launch_bounds__(256, 2)
void dist_mma(const float* __restrict__ x, float* __restrict__ out) {
    extern __shared__ float smf[];
    __shared__ float s_ni[BM], s_nj[BM];
    const uint32_t smb = smem_u32(smf);

    const int tid  = threadIdx.x;
    const int lane = tid & 31;
    const int w    = tid >> 5;
    const int wm   = w & 1;          // warp row (2 x 64)
    const int wn   = w >> 1;         // warp col (4 x 32)
    const int gid  = lane >> 2;      // 0..7
    const int tig  = lane & 3;       // 0..3

    // ldmatrix per-lane address offsets (bytes), within a fragment
    const uint32_t aoff = (uint32_t)(((lane & 15) * PITCH + 4 * (lane >> 4)) * 4);
    const uint32_t boff = (uint32_t)(((lane & 7) * PITCH + 4 * ((lane >> 3) & 1)) * 4);

    const int b = blockIdx.y;
    int p = blockIdx.x;
    int ti = 0;
    while (p >= NT - ti) { p -= NT - ti; ti++; }
    const int tj = ti + p;
    const int i0 = ti * BM, j0 = tj * BM;
    const bool diag = (ti == tj);

    const float* xb = x + (size_t)b * SEQ * KDIM;
    float* ob = out + (size_t)b * SEQ * SEQ;

    // preload norms into static smem (published by later syncthreads)
    if (tid < BM) s_ni[tid] = g_norms[b * SEQ + i0 + tid];
    else          s_nj[tid - BM] = g_norms[b * SEQ + j0 + tid - BM];

    // chunk loader: A tile rows i0.., B tile rows j0.., both [row][k] pitch 36
    auto load_chunk = [&](int c, int s) {
        const uint32_t base = smb + (uint32_t)s * (STAGE_F * 4);
#pragma unroll
        for (int t = 0; t < 4; t++) {
            const int idx = tid + t * 256;          // 1024 granules per tile
            const int row = idx >> 3;
            const int g   = idx & 7;
            const uint32_t off = (uint32_t)(row * (PITCH * 4) + g * 16);
            cp16(base + off,
                 xb + (size_t)(i0 + row) * KDIM + c * BK + g * 4);
            cp16(base + TILE_F * 4 + off,
                 xb + (size_t)(j0 + row) * KDIM + c * BK + g * 4);
        }
        CP_COMMIT();
    };

    float acc[4][4][4];
#pragma unroll
    for (int mt = 0; mt < 4; mt++)
#pragma unroll
        for (int nt = 0; nt < 4; nt++)
#pragma unroll
            for (int q = 0; q < 4; q++) acc[mt][nt][q] = 0.f;

    load_chunk(0, 0);
    load_chunk(1, 1);

    for (int c = 0; c < NCHUNK; c++) {
        if (c < NCHUNK - 1) { CP_WAIT(1); } else { CP_WAIT(0); }
        __syncthreads();

        const uint32_t As_u = smb +
            (uint32_t)(((c & 1) * STAGE_F + wm * 64 * PITCH) * 4) + aoff;
        const uint32_t Bs_u = smb +
            (uint32_t)(((c & 1) * STAGE_F + TILE_F + wn * 32 * PITCH) * 4) + boff;

#pragma unroll
        for (int kk = 0; kk < 4; kk++) {
            uint32_t af[4][4], bf[4][2];
#pragma unroll
            for (int mt = 0; mt < 4; mt++)
                ldsm_x4(As_u + (uint32_t)((mt * 16 * PITCH + kk * 8) * 4),
                        af[mt]);
#pragma unroll
            for (int nt = 0; nt < 4; nt++)
                ldsm_x2(Bs_u + (uint32_t)((nt * 8 * PITCH + kk * 8) * 4),
                        bf[nt]);
#pragma unroll
            for (int mt = 0; mt < 4; mt++)
#pragma unroll
                for (int nt = 0; nt < 4; nt++)
                    mma_tf32(acc[mt][nt], af[mt], bf[nt]);
        }
        __syncthreads();
        if (c + 2 < NCHUNK) load_chunk(c + 2, c & 1);
    }

    // -----------------------------------------------------------------------
    // Epilogue. Fragment (mt,nt): rows r0/r0+8, cols jc/jc+1.
    // Normal tile: direct float2 stores. Mirror: transpose-stage into the
    // (dead) pipeline smem [col][row] pitch 132, then coalesced float4 out.
    // -----------------------------------------------------------------------
    float* sd = smf;   // 128 x 132 floats = 16896 <= 18432 available
#pragma unroll
    for (int mt = 0; mt < 4; mt++) {
        const int r0 = wm * 64 + mt * 16 + gid;
        const int r1 = r0 + 8;
        const float n0 = s_ni[r0], n1 = s_ni[r1];
#pragma unroll
        for (int nt = 0; nt < 4; nt++) {
            const int jc = wn * 32 + nt * 8 + tig * 2;
            const float m0 = s_nj[jc], m1 = s_nj[jc + 1];
            float d00 = fmaxf(n0 + m0 - 2.f * acc[mt][nt][0], 0.f);
            float d01 = fmaxf(n0 + m1 - 2.f * acc[mt][nt][1], 0.f);
            float d10 = fmaxf(n1 + m0 - 2.f * acc[mt][nt][2], 0.f);
            float d11 = fmaxf(n1 + m1 - 2.f * acc[mt][nt][3], 0.f);
            if (diag) {
                if (r0 == jc)     d00 = 0.f;
                if (r0 == jc + 1) d01 = 0.f;
                if (r1 == jc)     d10 = 0.f;
                if (r1 == jc + 1) d11 = 0.f;
            }
            *(float2*)(ob + (size_t)(i0 + r0) * SEQ + j0 + jc) =
                make_float2(d00, d01);
            *(float2*)(ob + (size_t)(i0 + r1) * SEQ + j0 + jc) =
                make_float2(d10, d11);
            if (!diag) {
                sd[jc * 132 + r0]       = d00;
                sd[(jc + 1) * 132 + r0] = d01;
                sd[jc * 132 + r1]       = d10;
                sd[(jc + 1) * 132 + r1] = d11;
            }
        }
    }

    if (!diag) {
        __syncthreads();
        const int jr = tid >> 1;            // mirror row 0..127
        const int h  = tid & 1;             // half: 64 floats
        const float4* srow = (const float4*)(sd + jr * 132 + h * 64);
        float4* drow = (float4*)(ob + (size_t)(j0 + jr) * SEQ + i0 + h * 64);
#pragma unroll
        for (int q = 0; q < 16; q++) drow[q] = srow[q];
    }
}

// ---------------------------------------------------------------------------
extern "C" void kernel_launch(void* const* d_in, const int* in_sizes, int n_in,
                              void* d_out, int out_size) {
    const float* x = (const float*)d_in[0];
    float* out = (float*)d_out;
    (void)in_sizes; (void)n_in; (void)out_size;

    cudaFuncSetAttribute(dist_mma, cudaFuncAttributeMaxDynamicSharedMemorySize,
                         SMEM_BYTES);
    norms_kernel<<<(BATCH * SEQ + 7) / 8, 256>>>(x);
    dist_mma<<<dim3(NPAIR, BATCH), 256, SMEM_BYTES>>>(x, out);
}